// round 17
// baseline (speedup 1.0000x reference)
#include <cuda_runtime.h>
#include <cuda_fp16.h>
#include <cstdint>
#include <cstddef>

// ---------------- problem constants ----------------
#define B_TOTAL   32768
#define VN        10
#define C         128
#define NB        8
#define M_ROWS    80
#define GRID_FUSED 4096
#define THREADS_FUSED 320          // 10 warps
#define STATS_BLOCKS 1184
#define N4_TOTAL  10485760
#define CNT_INV   (1.0f / 327680.0f)
#define BN_EPS    1e-5f

// ---------------- smem layout ----------------
#define XS_STRH   136              // halfs per X/O row
#define QS_STRH   392              // halfs per qkv row
#define WS_STRH   136              // halfs per weight n-row
#define XS_OFF    0                // 80*136*2 = 21760
#define QS_OFF    21760            // 80*392*2 = 62720 (reused as Wk in P3)
#define WS_OFF    84480            // 64*136*2 = 17408
#define MK_OFF    101888           // 100*4
#define SMEM_BYTES 102288          // x2 CTAs/SM

// ---------------- device scratch ----------------
__device__ float g_part[STATS_BLOCKS * 256];
__device__ __align__(16) __half g_wqkvT[384 * 128];   // n-major, s-folded
__device__ float g_tw[384];                           // t @ w_qkv (fp32)
__device__ __align__(16) __half g_wkmh[128 * 128];    // w_out K-MAJOR fp16

// ---------------- helpers ----------------
__device__ __forceinline__ uint32_t smem_u32(const void* p) {
    uint32_t a;
    asm("{ .reg .u64 t; cvta.to.shared.u64 t, %1; cvt.u32.u64 %0, t; }" : "=r"(a) : "l"(p));
    return a;
}
__device__ __forceinline__ void mma16(float* c, const uint32_t* a, uint32_t b0, uint32_t b1) {
    asm volatile(
        "mma.sync.aligned.m16n8k16.row.col.f32.f16.f16.f32 "
        "{%0,%1,%2,%3}, {%4,%5,%6,%7}, {%8,%9}, {%0,%1,%2,%3};\n"
        : "+f"(c[0]), "+f"(c[1]), "+f"(c[2]), "+f"(c[3])
        : "r"(a[0]), "r"(a[1]), "r"(a[2]), "r"(a[3]), "r"(b0), "r"(b1));
}
#define LDSM4(r, addr) \
    asm volatile("ldmatrix.sync.aligned.m8n8.x4.shared.b16 {%0,%1,%2,%3}, [%4];" \
                 : "=r"((r)[0]), "=r"((r)[1]), "=r"((r)[2]), "=r"((r)[3]) : "r"(addr))

__device__ __forceinline__ void h8_to_f(uint4 u, float* f) {
    float2 t;
    t = __half22float2(*(__half2*)&u.x); f[0] = t.x; f[1] = t.y;
    t = __half22float2(*(__half2*)&u.y); f[2] = t.x; f[3] = t.y;
    t = __half22float2(*(__half2*)&u.z); f[4] = t.x; f[5] = t.y;
    t = __half22float2(*(__half2*)&u.w); f[6] = t.x; f[7] = t.y;
}

// ================= kernel 1: BN statistics (deterministic) =================
__global__ void __launch_bounds__(256) k_stats(const float4* __restrict__ x) {
    float sx = 0.f, sy = 0.f, sz = 0.f, sw = 0.f;
    float qx = 0.f, qy = 0.f, qz = 0.f, qw = 0.f;
    const int stride = STATS_BLOCKS * 256;   // mult of 32 -> fixed channel quad
    for (int i = blockIdx.x * 256 + threadIdx.x; i < N4_TOTAL; i += stride) {
        float4 v = x[i];
        sx += v.x; sy += v.y; sz += v.z; sw += v.w;
        qx += v.x * v.x; qy += v.y * v.y; qz += v.z * v.z; qw += v.w * v.w;
    }
    __shared__ float sh[4096];
    int w = threadIdx.x >> 5, l = threadIdx.x & 31;
    sh[w * 128 + l * 4 + 0] = sx; sh[w * 128 + l * 4 + 1] = sy;
    sh[w * 128 + l * 4 + 2] = sz; sh[w * 128 + l * 4 + 3] = sw;
    sh[2048 + w * 128 + l * 4 + 0] = qx; sh[2048 + w * 128 + l * 4 + 1] = qy;
    sh[2048 + w * 128 + l * 4 + 2] = qz; sh[2048 + w * 128 + l * 4 + 3] = qw;
    __syncthreads();
    int t = threadIdx.x;
    if (t < 128) {
        float a = 0.f;
        #pragma unroll
        for (int ww = 0; ww < 8; ++ww) a += sh[ww * 128 + t];
        g_part[blockIdx.x * 256 + t] = a;
    } else if (t < 256) {
        int u = t - 128;
        float a = 0.f;
        #pragma unroll
        for (int ww = 0; ww < 8; ++ww) a += sh[2048 + ww * 128 + u];
        g_part[blockIdx.x * 256 + t] = a;
    }
}

// ================= kernel 2: fold BN into weights =================
__global__ void __launch_bounds__(384) k_prep(
    const float* __restrict__ gamma, const float* __restrict__ beta,
    const float* __restrict__ wqkv, const float* __restrict__ wout)
{
    __shared__ float s_sum[256];
    __shared__ float s_s[128], s_t[128];
    int t = threadIdx.x;
    if (t < 256) {
        float a = 0.f;
        for (int b = 0; b < STATS_BLOCKS; ++b) a += g_part[b * 256 + t];
        s_sum[t] = a;
    }
    __syncthreads();
    if (t < 128) {
        float mean = s_sum[t] * CNT_INV;
        float var  = s_sum[128 + t] * CNT_INV - mean * mean;
        float rstd = 1.0f / sqrtf(var + BN_EPS);
        float sc = gamma[t] * rstd;
        s_s[t] = sc;
        s_t[t] = beta[t] - mean * sc;
    }
    __syncthreads();
    for (int k = 0; k < 128; ++k)
        g_wqkvT[t * 128 + k] = __float2half_rn(s_s[k] * wqkv[k * 384 + t]);
    {
        float a = 0.f;
        for (int k = 0; k < 128; ++k) a += s_t[k] * wqkv[k * 384 + t];
        g_tw[t] = a;
    }
    // w_out k-major fp16 (it's already k-major in the input)
    for (int i = t; i < 16384; i += 384)
        g_wkmh[i] = __float2half_rn(wout[i]);
}

// ================= kernel 3: fused (tensor qkv + FMA-pipe out-proj) =================
__global__ void __launch_bounds__(THREADS_FUSED, 2) k_fused(
    const float* __restrict__ x, const float* __restrict__ b_out,
    const float* __restrict__ mask, float* __restrict__ out)
{
    extern __shared__ __align__(16) char smraw[];
    __half* Xs = (__half*)(smraw + XS_OFF);
    __half* Qs = (__half*)(smraw + QS_OFF);
    __half* Ws = (__half*)(smraw + WS_OFF);
    float*  Mk = (float*)(smraw + MK_OFF);
    const uint32_t sbase = smem_u32(smraw);

    const int tid = threadIdx.x;
    const int warp = tid >> 5, lane = tid & 31;
    const int g = lane >> 2, tq = lane & 3;
    const int blk = blockIdx.x;

    const int mt = warp >> 1;     // m-tile (0..4)
    const int nh = warp & 1;      // n-half of the 64-wide chunk
    const int r0 = mt * 16 + g;

    // ldmatrix lane bases (byte smem addresses)
    const int lm = lane >> 3, lr = lane & 7;
    const uint32_t a_base = sbase + XS_OFF +
        (uint32_t)(((mt * 16 + (lm & 1) * 8 + lr) * XS_STRH + (lm >> 1) * 8) * 2);
    uint32_t b_base[2];
    #pragma unroll
    for (int ntp = 0; ntp < 2; ++ntp)
        b_base[ntp] = sbase + WS_OFF +
            (uint32_t)(((nh * 32 + ntp * 16 + (lm >> 1) * 8 + lr) * WS_STRH + (lm & 1) * 8) * 2);

    // ---- P0: stage X tile (fp16) + wqkv chunk0 + mask ----
    const float4* xg = (const float4*)(x + (size_t)blk * (NB * VN * C));
    #pragma unroll
    for (int it = 0; it < 8; ++it) {
        int idx = tid + it * THREADS_FUSED;      // 0..2559 (80 rows x 32 f4)
        int row = idx >> 5, c4 = idx & 31;
        float4 v = xg[idx];
        __half* dst = &Xs[row * XS_STRH + c4 * 4];
        *(__half2*)(dst + 0) = __floats2half2_rn(v.x, v.y);
        *(__half2*)(dst + 2) = __floats2half2_rn(v.z, v.w);
    }
    for (int u = tid; u < 1024; u += THREADS_FUSED) {
        int n = u >> 4, q = u & 15;
        ((uint4*)(Ws + n * WS_STRH))[q] = ((const uint4*)g_wqkvT)[u];
    }
    if (tid < 100) Mk[tid] = mask[tid];
    __syncthreads();

    // ---- preload A fragments via ldmatrix (8 x K16) ----
    uint32_t a[8][4];
    #pragma unroll
    for (int kk = 0; kk < 8; ++kk) LDSM4(a[kk], a_base + kk * 32);

    // ---- P1: qkv in 6 N-chunks of 64, register-prefetched weights (fp32 acc) ----
    for (int ch = 0; ch < 6; ++ch) {
        uint4 pf[4];
        const bool doPf = (ch < 5) && (tid < 256);
        if (doPf) {
            const uint4* wsrc = (const uint4*)(g_wqkvT + (ch + 1) * 64 * 128);
            #pragma unroll
            for (int j = 0; j < 4; ++j) pf[j] = wsrc[j * 256 + tid];
        }
        float acc[4][4];
        #pragma unroll
        for (int nt = 0; nt < 4; ++nt)
            #pragma unroll
            for (int j = 0; j < 4; ++j) acc[nt][j] = 0.f;
        #pragma unroll
        for (int kk = 0; kk < 8; ++kk) {
            #pragma unroll
            for (int ntp = 0; ntp < 2; ++ntp) {
                uint32_t bb[4];
                LDSM4(bb, b_base[ntp] + kk * 32);
                mma16(acc[ntp * 2 + 0], a[kk], bb[0], bb[1]);
                mma16(acc[ntp * 2 + 1], a[kk], bb[2], bb[3]);
            }
        }
        #pragma unroll
        for (int nt = 0; nt < 4; ++nt) {
            int col = ch * 64 + nh * 32 + nt * 8 + 2 * tq;
            float t0 = g_tw[col], t1 = g_tw[col + 1];
            *(__half2*)&Qs[r0 * QS_STRH + col] =
                __floats2half2_rn(acc[nt][0] + t0, acc[nt][1] + t1);
            *(__half2*)&Qs[(r0 + 8) * QS_STRH + col] =
                __floats2half2_rn(acc[nt][2] + t0, acc[nt][3] + t1);
        }
        __syncthreads();
        if (ch < 5) {
            if (doPf) {
                #pragma unroll
                for (int j = 0; j < 4; ++j) {
                    int u = j * 256 + tid;
                    int n = u >> 4, q = u & 15;
                    ((uint4*)(Ws + n * WS_STRH))[q] = pf[j];
                }
            }
            __syncthreads();
        }
    }

    // ---- P2: per-(batch,head) masked softmax; HFMA2 dots; O -> Xs fp16 ----
    {
        const int half = lane >> 4;
        const int i = lane & 15;
        const bool rowok = (i < VN);
        #pragma unroll
        for (int it = 0; it < 4; ++it) {
            int p = it * 20 + warp * 2 + half;
            bool act = (p < 64);
            int b = act ? (p >> 3) : 0;
            int h = act ? (p & 7) : 0;
            const __half* qbase = &Qs[(b * VN) * QS_STRH + h * 16];

            uint4 qv0, qv1;
            {
                const uint4* qr = (const uint4*)(qbase + (rowok ? i : 0) * QS_STRH);
                qv0 = qr[0]; qv1 = qr[1];
            }
            const __half2* qh0 = (const __half2*)&qv0;
            const __half2* qh1 = (const __half2*)&qv1;
            float mrow[VN];
            #pragma unroll
            for (int j = 0; j < VN; ++j)
                mrow[j] = Mk[(rowok ? i : 0) * VN + j] * 0.25f;

            float e[VN];
            float ssum = 0.f;
            #pragma unroll
            for (int j = 0; j < VN; ++j) {
                const uint4* kr = (const uint4*)(qbase + j * QS_STRH + 128);
                uint4 kv0 = kr[0], kv1 = kr[1];
                const __half2* kh0 = (const __half2*)&kv0;
                const __half2* kh1 = (const __half2*)&kv1;
                __half2 s = __hmul2(qh0[0], kh0[0]);
                s = __hfma2(qh0[1], kh0[1], s);
                s = __hfma2(qh0[2], kh0[2], s);
                s = __hfma2(qh0[3], kh0[3], s);
                s = __hfma2(qh1[0], kh1[0], s);
                s = __hfma2(qh1[1], kh1[1], s);
                s = __hfma2(qh1[2], kh1[2], s);
                s = __hfma2(qh1[3], kh1[3], s);
                float2 f = __half22float2(s);
                e[j] = __expf((f.x + f.y) * mrow[j]);
                ssum += e[j];
            }
            float o[16];
            #pragma unroll
            for (int d = 0; d < 16; ++d) o[d] = 0.f;
            #pragma unroll
            for (int j = 0; j < VN; ++j) {
                const uint4* vr = (const uint4*)(qbase + j * QS_STRH + 256);
                float vv[16];
                h8_to_f(vr[0], vv);
                h8_to_f(vr[1], vv + 8);
                float wj = e[j];
                #pragma unroll
                for (int d = 0; d < 16; ++d) o[d] += wj * vv[d];
            }
            if (act && rowok) {
                float inv = 1.0f / ssum;
                __half2 hp[8];
                #pragma unroll
                for (int d = 0; d < 8; ++d)
                    hp[d] = __floats2half2_rn(o[2 * d] * inv, o[2 * d + 1] * inv);
                uint4* dst = (uint4*)&Xs[(b * VN + i) * XS_STRH + h * 16];
                dst[0] = *(uint4*)&hp[0];
                dst[1] = *(uint4*)&hp[4];
            }
        }
    }
    __syncthreads();   // O ready in Xs; Qs free

    // ---- P3: out = O @ w_out + b_out on the FMA pipe ----
    // Stage w_out k-major fp16 into the dead Qs region (128 rows x 128 halfs).
    __half* Wk = Qs;
    for (int u = tid; u < 2048; u += THREADS_FUSED)
        ((uint4*)Wk)[u] = ((const uint4*)g_wkmh)[u];
    __syncthreads();

    {
        const int r0w = warp * 8;                     // 10 warps x 8 rows = 80
        const float4 bo = *(const float4*)&b_out[lane * 4];
        float4 accf[8];
        #pragma unroll
        for (int r = 0; r < 8; ++r) accf[r] = make_float4(0.f, 0.f, 0.f, 0.f);

        #pragma unroll
        for (int kb = 0; kb < 8; ++kb) {              // 8 chunks of 16 k
            __half2 acch[8][2];
            #pragma unroll
            for (int r = 0; r < 8; ++r) {
                acch[r][0] = __float2half2_rn(0.f);
                acch[r][1] = __float2half2_rn(0.f);
            }
            #pragma unroll
            for (int k2 = 0; k2 < 8; ++k2) {          // 2 k-rows per iter
                int k = kb * 16 + k2 * 2;
                uint2 w0 = *(const uint2*)&Wk[(k + 0) * 128 + lane * 4];
                uint2 w1 = *(const uint2*)&Wk[(k + 1) * 128 + lane * 4];
                #pragma unroll
                for (int r = 0; r < 8; ++r) {
                    __half2 ov = *(const __half2*)&Xs[(r0w + r) * XS_STRH + k];
                    __half2 olo = __low2half2(ov);
                    __half2 ohi = __high2half2(ov);
                    acch[r][0] = __hfma2(olo, *(__half2*)&w0.x, acch[r][0]);
                    acch[r][1] = __hfma2(olo, *(__half2*)&w0.y, acch[r][1]);
                    acch[r][0] = __hfma2(ohi, *(__half2*)&w1.x, acch[r][0]);
                    acch[r][1] = __hfma2(ohi, *(__half2*)&w1.y, acch[r][1]);
                }
            }
            #pragma unroll
            for (int r = 0; r < 8; ++r) {             // flush chunk to fp32
                float2 f0 = __half22float2(acch[r][0]);
                float2 f1 = __half22float2(acch[r][1]);
                accf[r].x += f0.x; accf[r].y += f0.y;
                accf[r].z += f1.x; accf[r].w += f1.y;
            }
        }
        #pragma unroll
        for (int r = 0; r < 8; ++r) {
            size_t ro = ((size_t)blk * M_ROWS + r0w + r) * C + lane * 4;
            *(float4*)&out[ro] = make_float4(accf[r].x + bo.x, accf[r].y + bo.y,
                                             accf[r].z + bo.z, accf[r].w + bo.w);
        }
    }
}

// ================= launch =================
extern "C" void kernel_launch(void* const* d_in, const int* in_sizes, int n_in,
                              void* d_out, int out_size) {
    const float* x     = (const float*)d_in[0];
    const float* gamma = (const float*)d_in[1];
    const float* beta  = (const float*)d_in[2];
    const float* wqkv  = (const float*)d_in[3];
    const float* wout  = (const float*)d_in[4];
    const float* bout  = (const float*)d_in[5];
    const float* mask  = (const float*)d_in[6];

    cudaFuncSetAttribute(k_fused, cudaFuncAttributeMaxDynamicSharedMemorySize, SMEM_BYTES);

    k_stats<<<STATS_BLOCKS, 256>>>((const float4*)x);
    k_prep<<<1, 384>>>(gamma, beta, wqkv, wout);
    k_fused<<<GRID_FUSED, THREADS_FUSED, SMEM_BYTES>>>(x, bout, mask, (float*)d_out);
}